// round 11
// baseline (speedup 1.0000x reference)
#include <cuda_runtime.h>
#include <cuda_bf16.h>

// Problem constants (fixed by the reference)
#define Cc    8
#define Ll    4096
#define Ff    32
#define Kk    10
#define PROC  20
#define STEP  5
#define NWIN  815          // == CHAN_OUT, no pad region
#define WPB   416          // threads per block (13 warps); 2 windows/thread
#define WINPB 832          // window slots per block (covers all 815, 2% waste)

// Shared x tile: covers WINPB windows -> WINPB*STEP + (PROC-STEP) = 4175 floats
#define SXN (WINPB * STEP + PROC - STEP)

// Exact 3-way float min for NONNEGATIVE floats via DPX (single VIMNMX3):
// IEEE nonneg floats order identically to their int bit patterns.
__device__ __forceinline__ float fmin3_nonneg(float a, float b, float c)
{
    return __int_as_float(__vimin3_s32(__float_as_int(a),
                                       __float_as_int(b),
                                       __float_as_int(c)));
}

// Pin a value into a register: the empty asm breaks rematerialization
// provenance so ptxas cannot re-issue the originating LDS at each use.
__device__ __forceinline__ float pin(float v)
{
    asm("" : "+f"(v));
    return v;
}

__global__ __launch_bounds__(WPB, 2)
void dtw_kernel(const float* __restrict__ x,
                const float* __restrict__ kernels,
                float* __restrict__ out)
{
    const int f   = blockIdx.x;           // filter  [0, Ff)
    const int bc  = blockIdx.y;           // b*C + c [0, 64)
    const int tid = threadIdx.x;

    __shared__ float sx[SXN];
    __shared__ float sk[Kk];

    // Kernel taps -> shared: frees 10 registers; read back as one broadcast
    // LDS per row (10 total, negligible).
    if (tid < Kk) sk[tid] = kernels[f * Kk + tid];

    // Cooperative, coalesced load of the whole channel for this (b,c)
    const float* xc = x + (size_t)bc * Ll;
    #pragma unroll
    for (int i = tid; i < SXN; i += WPB) {
        sx[i] = (i < Ll) ? xc[i] : 0.0f;
    }
    __syncthreads();

    // This thread owns adjacent windows g0 = 2*tid and g0+1.
    const int g0 = 2 * tid;
    if (g0 >= NWIN) return;               // only 8 threads exit; no syncs below

    // 25-float span covers BOTH windows: w0[j] = s[j], w1[j] = s[j+5].
    // pin() forces all 25 into REGISTERS (measured: without it, ptxas holds
    // only 47 regs and re-issues an LDS per use -> +1.6 instr/cell).
    float s[PROC + STEP];
    #pragma unroll
    for (int j = 0; j < PROC + STEP; j++) s[j] = pin(sx[g0 * STEP + j]);

    // Two independent DTW tables, interleaved for ILP=2. Fully unrolled:
    // register renaming kills all rotation MOVs.
    float a0[PROC], a1[PROC];

    // Row 0: cumulative sum of squared diffs
    {
        const float k0 = sk[0];
        float d0 = k0 - s[0];
        float d1 = k0 - s[STEP];
        a0[0] = d0 * d0;
        a1[0] = d1 * d1;
        #pragma unroll
        for (int j = 1; j < PROC; j++) {
            d0 = k0 - s[j];
            d1 = k0 - s[j + STEP];
            a0[j] = fmaf(d0, d0, a0[j - 1]);
            a1[j] = fmaf(d1, d1, a1[j - 1]);
        }
    }

    // Rows 1..K-1. Single DPX 3-way min per cell (values >= 0 so int-ordered
    // min is exact); serial path per cell = VIMNMX3 + FFMA.
    #pragma unroll
    for (int i = 1; i < Kk; i++) {
        const float kv = sk[i];           // one broadcast LDS per row
        float dg0 = a0[0];
        float dg1 = a1[0];
        float d0 = kv - s[0];
        float d1 = kv - s[STEP];
        a0[0] = fmaf(d0, d0, a0[0]);
        a1[0] = fmaf(d1, d1, a1[0]);
        #pragma unroll
        for (int j = 1; j < PROC; j++) {
            const float up0 = a0[j];
            const float up1 = a1[j];
            const float m0  = fmin3_nonneg(a0[j - 1], up0, dg0);
            const float m1  = fmin3_nonneg(a1[j - 1], up1, dg1);
            d0 = kv - s[j];
            d1 = kv - s[j + STEP];
            a0[j] = fmaf(d0, d0, m0);
            a1[j] = fmaf(d1, d1, m1);
            dg0 = up0;                            // renamed away by unroll
            dg1 = up1;
        }
    }

    // out[b, c*F + f, w]: coalesced in w (two adjacent elements per thread)
    const size_t o = ((size_t)bc * Ff + f) * NWIN + g0;
    out[o] = a0[PROC - 1];
    if (g0 + 1 < NWIN) out[o + 1] = a1[PROC - 1];
}

extern "C" void kernel_launch(void* const* d_in, const int* in_sizes, int n_in,
                              void* d_out, int out_size)
{
    const float* x       = (const float*)d_in[0];   // (8, 8, 4096) f32
    const float* kernels = (const float*)d_in[1];   // (32, 10) f32
    float*       out     = (float*)d_out;           // (8, 256, 815) f32

    (void)in_sizes; (void)n_in; (void)out_size;

    dim3 grid(Ff, 8 * Cc);   // (32, 64) -> 2048 blocks
    dtw_kernel<<<grid, WPB>>>(x, kernels, out);
}

// round 12
// speedup vs baseline: 1.2011x; 1.2011x over previous
#include <cuda_runtime.h>
#include <cuda_bf16.h>

// Problem constants (fixed by the reference)
#define Cc    8
#define Ll    4096
#define Ff    32
#define Kk    10
#define PROC  20
#define STEP  5
#define NWIN  815          // == CHAN_OUT, no pad region
#define WPB   416          // threads per block (13 warps); 2 windows/thread
#define WINPB 832          // window slots per block (covers all 815, 2% waste)
#define SPAN  (PROC + STEP) // 25-sample span covering both windows

// Shared x tile: covers WINPB windows -> WINPB*STEP + (PROC-STEP) = 4175 floats
#define SXN (WINPB * STEP + PROC - STEP)

// Exact 3-way float min for NONNEGATIVE floats via DPX (single VIMNMX3):
// IEEE nonneg floats order identically to their int bit patterns.
__device__ __forceinline__ float fmin3_nonneg(float a, float b, float c)
{
    return __int_as_float(__vimin3_s32(__float_as_int(a),
                                       __float_as_int(b),
                                       __float_as_int(c)));
}

__global__ __launch_bounds__(WPB, 3)
void dtw_kernel(const float* __restrict__ x,
                const float* __restrict__ kernels,
                float* __restrict__ out)
{
    const int f   = blockIdx.x;           // filter  [0, Ff)
    const int bc  = blockIdx.y;           // b*C + c [0, 64)
    const int tid = threadIdx.x;

    __shared__ float sx[SXN];

    // Cooperative, coalesced load of the whole channel for this (b,c)
    const float* xc = x + (size_t)bc * Ll;
    #pragma unroll
    for (int i = tid; i < SXN; i += WPB) {
        sx[i] = (i < Ll) ? xc[i] : 0.0f;
    }
    __syncthreads();

    // This thread owns adjacent windows g0 = 2*tid and g0+1.
    const int g0 = 2 * tid;
    if (g0 >= NWIN) return;               // only 8 threads exit; no syncs below

    // Kernel taps: warp-uniform addresses -> broadcast loads, L1-resident
    float ker[Kk];
    #pragma unroll
    for (int i = 0; i < Kk; i++) ker[i] = __ldg(&kernels[f * Kk + i]);

    // Window samples stay in SHARED; ptxas remats the LDS at use sites, which
    // measured cheaper than pinning them into registers (R11 lesson).
    const int sbase = g0 * STEP;

    // Two DTW tables: window 0 = s[0..19], window 1 = s[5..24].
    // Single jj-sweep computes df = kv - s[jj] ONCE and feeds BOTH windows
    // (w0 cell jj, w1 cell jj-5): FADD count 25/row-pair instead of 40.
    float a0[PROC], a1[PROC];

    // Row 0: cumulative sum of squared diffs, shared df
    {
        const float k0 = ker[0];
        #pragma unroll
        for (int jj = 0; jj < SPAN; jj++) {
            const float df = k0 - sx[sbase + jj];
            if (jj < PROC) {
                a0[jj] = (jj == 0) ? df * df : fmaf(df, df, a0[jj - 1]);
            }
            if (jj >= STEP) {
                const int j = jj - STEP;
                a1[j] = (j == 0) ? df * df : fmaf(df, df, a1[j - 1]);
            }
        }
    }

    // Rows 1..K-1: same shared-df sweep. DPX 3-way min (values >= 0, exact);
    // serial path per cell = VIMNMX3 + FFMA; the two chains are staggered by
    // 5 columns, which helps pipelining. Fully unrolled: no rotation MOVs.
    #pragma unroll
    for (int i = 1; i < Kk; i++) {
        const float kv = ker[i];
        float dg0 = 0.0f, dg1 = 0.0f;     // diag carries (init dead)
        #pragma unroll
        for (int jj = 0; jj < SPAN; jj++) {
            const float df = kv - sx[sbase + jj];
            if (jj < PROC) {
                const int j = jj;
                if (j == 0) {
                    dg0 = a0[0];
                    a0[0] = fmaf(df, df, a0[0]);
                } else {
                    const float up = a0[j];
                    const float m  = fmin3_nonneg(a0[j - 1], up, dg0);
                    a0[j] = fmaf(df, df, m);
                    dg0 = up;
                }
            }
            if (jj >= STEP) {
                const int j = jj - STEP;
                if (j == 0) {
                    dg1 = a1[0];
                    a1[0] = fmaf(df, df, a1[0]);
                } else {
                    const float up = a1[j];
                    const float m  = fmin3_nonneg(a1[j - 1], up, dg1);
                    a1[j] = fmaf(df, df, m);
                    dg1 = up;
                }
            }
        }
    }

    // out[b, c*F + f, w]: coalesced in w (two adjacent elements per thread)
    const size_t o = ((size_t)bc * Ff + f) * NWIN + g0;
    out[o] = a0[PROC - 1];
    if (g0 + 1 < NWIN) out[o + 1] = a1[PROC - 1];
}

extern "C" void kernel_launch(void* const* d_in, const int* in_sizes, int n_in,
                              void* d_out, int out_size)
{
    const float* x       = (const float*)d_in[0];   // (8, 8, 4096) f32
    const float* kernels = (const float*)d_in[1];   // (32, 10) f32
    float*       out     = (float*)d_out;           // (8, 256, 815) f32

    (void)in_sizes; (void)n_in; (void)out_size;

    dim3 grid(Ff, 8 * Cc);   // (32, 64) -> 2048 blocks
    dtw_kernel<<<grid, WPB>>>(x, kernels, out);
}

// round 13
// speedup vs baseline: 1.2506x; 1.0412x over previous
#include <cuda_runtime.h>
#include <cuda_bf16.h>

// Problem constants (fixed by the reference)
#define Cc    8
#define Ll    4096
#define Ff    32
#define Kk    10
#define PROC  20
#define STEP  5
#define NWIN  815          // == CHAN_OUT, no pad region
#define WPB   416          // threads per block (13 warps); 2 windows/thread
#define WINPB 832          // window slots per block (covers all 815, 2% waste)
#define SPAN  (PROC + STEP) // 25-sample span covering both windows
#define FPB   2            // filters per block (f and f+16), rolled loop
#define FGRID (Ff / FPB)   // 16

// Shared x tile: covers WINPB windows -> WINPB*STEP + (PROC-STEP) = 4175 floats
#define SXN (WINPB * STEP + PROC - STEP)

// Exact 3-way float min for NONNEGATIVE floats via DPX (single VIMNMX3):
// IEEE nonneg floats order identically to their int bit patterns.
__device__ __forceinline__ float fmin3_nonneg(float a, float b, float c)
{
    return __int_as_float(__vimin3_s32(__float_as_int(a),
                                       __float_as_int(b),
                                       __float_as_int(c)));
}

__global__ __launch_bounds__(WPB, 3)
void dtw_kernel(const float* __restrict__ x,
                const float* __restrict__ kernels,
                float* __restrict__ out)
{
    const int fp  = blockIdx.x;           // filter pair [0, 16): f = fp, fp+16
    const int bc  = blockIdx.y;           // b*C + c [0, 64)
    const int tid = threadIdx.x;

    __shared__ float sx[SXN];

    // Cooperative, coalesced load of the whole channel for this (b,c).
    // Loaded ONCE, reused by both filters of this block.
    const float* xc = x + (size_t)bc * Ll;
    #pragma unroll
    for (int i = tid; i < SXN; i += WPB) {
        sx[i] = (i < Ll) ? xc[i] : 0.0f;
    }
    __syncthreads();

    // This thread owns adjacent windows g0 = 2*tid and g0+1.
    const int g0 = 2 * tid;
    if (g0 >= NWIN) return;               // only 8 threads exit; no syncs below

    const int sbase = g0 * STEP;

    // Rolled loop over the block's two filters. Nothing FP-live crosses the
    // loop boundary (acc arrays re-initialized), so no rotation-MOV cost;
    // rolled keeps code ~21KB (I$ L1.5-resident).
    #pragma unroll 1
    for (int ff = 0; ff < FPB; ff++) {
        const int f = fp + ff * FGRID;

        // Kernel taps: warp-uniform addresses -> broadcast loads, L1-resident
        float ker[Kk];
        #pragma unroll
        for (int i = 0; i < Kk; i++) ker[i] = __ldg(&kernels[f * Kk + i]);

        // Two DTW tables: window 0 = s[0..19], window 1 = s[5..24].
        // Window samples stay in SHARED (remat-LDS beat pinned regs, R11).
        float a0[PROC], a1[PROC];

        // Row 0: cumulative sum of squared diffs, df shared between windows
        {
            const float k0 = ker[0];
            #pragma unroll
            for (int jj = 0; jj < SPAN; jj++) {
                const float df = k0 - sx[sbase + jj];
                if (jj < PROC) {
                    a0[jj] = (jj == 0) ? df * df : fmaf(df, df, a0[jj - 1]);
                }
                if (jj >= STEP) {
                    const int j = jj - STEP;
                    a1[j] = (j == 0) ? df * df : fmaf(df, df, a1[j - 1]);
                }
            }
        }

        // Rows 1..K-1: DPX 3-way min (values >= 0, exact); serial path per
        // cell = VIMNMX3 + FFMA; chains staggered by 5 columns. Fully unrolled.
        #pragma unroll
        for (int i = 1; i < Kk; i++) {
            const float kv = ker[i];
            float dg0 = 0.0f, dg1 = 0.0f; // diag carries (init dead)
            #pragma unroll
            for (int jj = 0; jj < SPAN; jj++) {
                const float df = kv - sx[sbase + jj];
                if (jj < PROC) {
                    const int j = jj;
                    if (j == 0) {
                        dg0 = a0[0];
                        a0[0] = fmaf(df, df, a0[0]);
                    } else {
                        const float up = a0[j];
                        const float m  = fmin3_nonneg(a0[j - 1], up, dg0);
                        a0[j] = fmaf(df, df, m);
                        dg0 = up;
                    }
                }
                if (jj >= STEP) {
                    const int j = jj - STEP;
                    if (j == 0) {
                        dg1 = a1[0];
                        a1[0] = fmaf(df, df, a1[0]);
                    } else {
                        const float up = a1[j];
                        const float m  = fmin3_nonneg(a1[j - 1], up, dg1);
                        a1[j] = fmaf(df, df, m);
                        dg1 = up;
                    }
                }
            }
        }

        // out[b, c*F + f, w]: coalesced in w (two adjacent elements/thread)
        const size_t o = ((size_t)bc * Ff + f) * NWIN + g0;
        out[o] = a0[PROC - 1];
        if (g0 + 1 < NWIN) out[o + 1] = a1[PROC - 1];
    }
}

extern "C" void kernel_launch(void* const* d_in, const int* in_sizes, int n_in,
                              void* d_out, int out_size)
{
    const float* x       = (const float*)d_in[0];   // (8, 8, 4096) f32
    const float* kernels = (const float*)d_in[1];   // (32, 10) f32
    float*       out     = (float*)d_out;           // (8, 256, 815) f32

    (void)in_sizes; (void)n_in; (void)out_size;

    dim3 grid(FGRID, 8 * Cc);   // (16, 64) -> 1024 blocks
    dtw_kernel<<<grid, WPB>>>(x, kernels, out);
}

// round 14
// speedup vs baseline: 1.2655x; 1.0119x over previous
#include <cuda_runtime.h>
#include <cuda_bf16.h>

// Problem constants (fixed by the reference)
#define Cc    8
#define Ll    4096
#define Ff    32
#define Kk    10
#define PROC  20
#define STEP  5
#define NWIN  815          // == CHAN_OUT, no pad region
#define WPB   416          // threads per block (13 warps); 2 windows/thread
#define WINPB 832          // window slots per block (covers all 815, 2% waste)
#define SPAN  (PROC + STEP) // 25-sample span covering both windows
#define FPB   2            // filters per block (f and f+16), rolled loop
#define FGRID (Ff / FPB)   // 16

// Shared x tile: covers WINPB windows -> WINPB*STEP + (PROC-STEP) = 4175 floats
#define SXN (WINPB * STEP + PROC - STEP)

// Exact 3-way float min for NONNEGATIVE floats via DPX (single VIMNMX3):
// IEEE nonneg floats order identically to their int bit patterns.
__device__ __forceinline__ float fmin3_nonneg(float a, float b, float c)
{
    return __int_as_float(__vimin3_s32(__float_as_int(a),
                                       __float_as_int(b),
                                       __float_as_int(c)));
}

// One DTW cell-pair update at span position JJ with shared df.
// JJ is a compile-time constant after unrolling -> a0/a1 stay in registers.
#define DO_CELL(JJ, DF)                                                        \
    do {                                                                       \
        const float _df = (DF);                                                \
        if ((JJ) < PROC) {                                                     \
            if ((JJ) == 0) {                                                   \
                dg0 = a0[0];                                                   \
                a0[0] = fmaf(_df, _df, a0[0]);                                 \
            } else {                                                           \
                const float up = a0[(JJ)];                                     \
                const float m  = fmin3_nonneg(a0[(JJ) - 1], up, dg0);          \
                a0[(JJ)] = fmaf(_df, _df, m);                                  \
                dg0 = up;                                                      \
            }                                                                  \
        }                                                                      \
        if ((JJ) >= STEP) {                                                    \
            const int _j1 = (JJ) - STEP;                                       \
            if (_j1 == 0) {                                                    \
                dg1 = a1[0];                                                   \
                a1[0] = fmaf(_df, _df, a1[0]);                                 \
            } else {                                                           \
                const float up = a1[_j1];                                      \
                const float m  = fmin3_nonneg(a1[_j1 - 1], up, dg1);           \
                a1[_j1] = fmaf(_df, _df, m);                                   \
                dg1 = up;                                                      \
            }                                                                  \
        }                                                                      \
    } while (0)

// Row-0 (cumsum) variant
#define DO_CELL0(JJ, DF)                                                       \
    do {                                                                       \
        const float _df = (DF);                                                \
        if ((JJ) < PROC)                                                       \
            a0[(JJ)] = ((JJ) == 0) ? _df * _df : fmaf(_df, _df, a0[(JJ) - 1]); \
        if ((JJ) >= STEP) {                                                    \
            const int _j1 = (JJ) - STEP;                                       \
            a1[_j1] = (_j1 == 0) ? _df * _df : fmaf(_df, _df, a1[_j1 - 1]);    \
        }                                                                      \
    } while (0)

__global__ __launch_bounds__(WPB, 3)
void dtw_kernel(const float* __restrict__ x,
                const float* __restrict__ kernels,
                float* __restrict__ out)
{
    const int fp  = blockIdx.x;           // filter pair [0, 16): f = fp, fp+16
    const int bc  = blockIdx.y;           // b*C + c [0, 64)
    const int tid = threadIdx.x;

    __shared__ float sx[SXN];

    // Vectorized fill: 1024 float4s cover [0, 4096); zero-fill the 79-float tail.
    const float4* xc4 = (const float4*)(x + (size_t)bc * Ll);
    #pragma unroll
    for (int i = tid; i < Ll / 4; i += WPB) {
        *reinterpret_cast<float4*>(&sx[i * 4]) = xc4[i];
    }
    if (Ll + tid < SXN) sx[Ll + tid] = 0.0f;
    __syncthreads();

    // This thread owns adjacent windows g0 = 2*tid and g0+1.
    const int g0 = 2 * tid;
    if (g0 >= NWIN) return;               // only 8 threads exit; no syncs below

    const int sbase = g0 * STEP;          // = 10*tid: EVEN -> float2-aligned

    // Rolled loop over the block's two filters (I$-friendly; no FP state
    // crosses the boundary so no rotation-MOV cost).
    #pragma unroll 1
    for (int ff = 0; ff < FPB; ff++) {
        const int f = fp + ff * FGRID;

        // Kernel taps: warp-uniform addresses -> broadcast loads, L1-resident
        float ker[Kk];
        #pragma unroll
        for (int i = 0; i < Kk; i++) ker[i] = __ldg(&kernels[f * Kk + i]);

        // Two DTW tables: window 0 = span[0..19], window 1 = span[5..24].
        // Span samples read from SHARED as float2 pairs: 13 LDS.64 per row
        // instead of 25 LDS.32 (stride-10 float2 across lanes: conflict-free).
        float a0[PROC], a1[PROC];

        // Row 0: cumulative sum of squared diffs, df shared between windows
        {
            const float k0 = ker[0];
            #pragma unroll
            for (int p = 0; p < SPAN / 2; p++) {
                const float2 sp = *reinterpret_cast<const float2*>(&sx[sbase + 2 * p]);
                DO_CELL0(2 * p,     k0 - sp.x);
                DO_CELL0(2 * p + 1, k0 - sp.y);
            }
            DO_CELL0(SPAN - 1, k0 - sx[sbase + SPAN - 1]);
        }

        // Rows 1..K-1: DPX 3-way min; serial path per cell = VIMNMX3 + FFMA;
        // the two windows' chains are staggered by 5 columns. Fully unrolled.
        #pragma unroll
        for (int i = 1; i < Kk; i++) {
            const float kv = ker[i];
            float dg0 = 0.0f, dg1 = 0.0f; // diag carries (init dead)
            #pragma unroll
            for (int p = 0; p < SPAN / 2; p++) {
                const float2 sp = *reinterpret_cast<const float2*>(&sx[sbase + 2 * p]);
                DO_CELL(2 * p,     kv - sp.x);
                DO_CELL(2 * p + 1, kv - sp.y);
            }
            DO_CELL(SPAN - 1, kv - sx[sbase + SPAN - 1]);
        }

        // out[b, c*F + f, w]: coalesced in w (two adjacent elements/thread)
        const size_t o = ((size_t)bc * Ff + f) * NWIN + g0;
        out[o] = a0[PROC - 1];
        if (g0 + 1 < NWIN) out[o + 1] = a1[PROC - 1];
    }
}

extern "C" void kernel_launch(void* const* d_in, const int* in_sizes, int n_in,
                              void* d_out, int out_size)
{
    const float* x       = (const float*)d_in[0];   // (8, 8, 4096) f32
    const float* kernels = (const float*)d_in[1];   // (32, 10) f32
    float*       out     = (float*)d_out;           // (8, 256, 815) f32

    (void)in_sizes; (void)n_in; (void)out_size;

    dim3 grid(FGRID, 8 * Cc);   // (16, 64) -> 1024 blocks
    dtw_kernel<<<grid, WPB>>>(x, kernels, out);
}